// round 14
// baseline (speedup 1.0000x reference)
#include <cuda_runtime.h>
#include <cuda_bf16.h>
#include <math.h>
#include <cstdint>

#define Bc 32
#define Nn 2048
#define Ee 4096
#define HC 256
#define NH 4
#define EN (Ee + Nn)              // 6144
#define TOT_NODES (Bc * Nn)       // 65536
#define TOT_EDGES (Bc * EN)       // 196608
#define KA 512                    // stored A split width (hi|lo)
#define KB 768                    // B split width (hi|hi|lo) == GEMM K

// ---------------- scratch (device globals) ----------------
__device__ float         g_h  [TOT_NODES * HC];
__device__ float         g_x2 [TOT_NODES * HC];
__device__ __nv_bfloat16 g_ae [(size_t)TOT_NODES * KA];
__device__ __nv_bfloat16 g_be1[256 * KB];
__device__ __nv_bfloat16 g_be2[256 * KB];
__device__ float         g_asrc[TOT_NODES * NH];
__device__ float         g_adst[TOT_NODES * NH];
__device__ unsigned      g_m  [TOT_NODES * NH];
__device__ float         g_den[TOT_NODES * NH];
__device__ float         g_e  [TOT_EDGES * NH];
// CSR (built once per call; shared by both layers)
__device__ int           g_cnt[TOT_NODES];
__device__ int           g_cur[TOT_NODES];
__device__ int           g_off[TOT_NODES];
__device__ int           g_eid[TOT_EDGES];

__device__ __forceinline__ uint32_t smem_u32(const void* p) {
    uint32_t a;
    asm("{ .reg .u64 t; cvta.to.shared.u64 t, %1; cvt.u32.u64 %0, t; }"
        : "=r"(a) : "l"(p));
    return a;
}

#define CP_ASYNC16(dst, src) \
    asm volatile("cp.async.ca.shared.global [%0], [%1], 16;" :: "r"(dst), "l"(src))
#define CP_COMMIT() asm volatile("cp.async.commit_group;" ::: "memory")
#define CP_WAIT1()  asm volatile("cp.async.wait_group 1;" ::: "memory")
#define CP_WAIT0()  asm volatile("cp.async.wait_group 0;" ::: "memory")

#define LDSM4(R, addr) \
    asm volatile("ldmatrix.sync.aligned.m8n8.x4.shared.b16 {%0,%1,%2,%3}, [%4];" \
        : "=r"((R)[0]), "=r"((R)[1]), "=r"((R)[2]), "=r"((R)[3]) : "r"(addr))

#define MMA16816(c, a, b0r, b1r) \
    asm volatile("mma.sync.aligned.m16n8k16.row.col.f32.bf16.bf16.f32 " \
        "{%0,%1,%2,%3}, {%4,%5,%6,%7}, {%8,%9}, {%0,%1,%2,%3};" \
        : "+f"((c)[0]), "+f"((c)[1]), "+f"((c)[2]), "+f"((c)[3]) \
        : "r"((a)[0]), "r"((a)[1]), "r"((a)[2]), "r"((a)[3]), "r"(b0r), "r"(b1r))

// ---------------- bf16 HMMA GEMM, warp tile 64x64, fused attn dots ----------
// H[M,256] = Ae3[M,768] @ Be[256,768]^T (Ae3 col k -> stored col k%512).
// CTA 128x128, 128 threads (4 warps, 2x2), BK=32, cp.async double buffer.
// Epilogue: g_asrc/g_adst[row,head] += sum_col H[row,col]*att[col] (atomic).
#define ROWB 40
#define TILE_B (128 * ROWB * 2)   // bytes per buffer (A or B)

__global__ __launch_bounds__(128, 2) void gemm_bf16(
    const __nv_bfloat16* __restrict__ Ae, const __nv_bfloat16* __restrict__ Be,
    float* __restrict__ Hout,
    const float* __restrict__ att_s, const float* __restrict__ att_d) {

    __shared__ __align__(16) __nv_bfloat16 sA[2][128][ROWB];
    __shared__ __align__(16) __nv_bfloat16 sB[2][128][ROWB];
    __shared__ float s_atts[256], s_attd[256];

    const int tid = threadIdx.x;
    const int wid = tid >> 5, lane = tid & 31;
    const int wm = (wid & 1) * 64;
    const int wn = (wid >> 1) * 64;
    const long bm = (long)blockIdx.x * 128;
    const int  bn = blockIdx.y * 128;

    s_atts[tid] = att_s[tid];       s_attd[tid] = att_d[tid];
    s_atts[tid + 128] = att_s[tid + 128]; s_attd[tid + 128] = att_d[tid + 128];

    const uint32_t sA_u = smem_u32(&sA[0][0][0]);
    const uint32_t sB_u = smem_u32(&sB[0][0][0]);

    float acc[4][8][4];
#pragma unroll
    for (int i = 0; i < 4; i++)
#pragma unroll
        for (int j = 0; j < 8; j++)
#pragma unroll
            for (int r = 0; r < 4; r++) acc[i][j][r] = 0.f;

    const int lr = tid >> 2;        // 0..31
    const int lc = tid & 3;         // 16B chunk

    auto loadAB = [&](int chunk, int buf) {
        int k = chunk * 32 + lc * 8;
        int sk = (k < KA) ? k : k - KA;
#pragma unroll
        for (int i = 0; i < 4; i++) {
            int r = lr + i * 32;
            CP_ASYNC16(sA_u + buf * TILE_B + r * 80 + lc * 16,
                       Ae + (size_t)(bm + r) * KA + sk);
            CP_ASYNC16(sB_u + buf * TILE_B + r * 80 + lc * 16,
                       Be + (size_t)(bn + r) * KB + k);
        }
    };

    loadAB(0, 0);
    CP_COMMIT();

    const int NCH = KB / 32;   // 24
#pragma unroll 1
    for (int c = 0; c < NCH; c++) {
        int buf = c & 1;
        if (c + 1 < NCH) { loadAB(c + 1, buf ^ 1); CP_COMMIT(); CP_WAIT1(); }
        else            { CP_WAIT0(); }
        __syncthreads();

        const uint32_t aBase = sA_u + buf * TILE_B;
        const uint32_t bBase = sB_u + buf * TILE_B;
#pragma unroll
        for (int kk = 0; kk < 32; kk += 16) {
            uint32_t af[4][4];
#pragma unroll
            for (int mt = 0; mt < 4; mt++) {
                int row = wm + mt * 16 + (lane & 15);
                int col = kk + ((lane >= 16) ? 8 : 0);
                LDSM4(af[mt], aBase + row * 80 + col * 2);
            }
            uint32_t bf[4][4];
#pragma unroll
            for (int q = 0; q < 4; q++) {
                int row = wn + q * 16 + (lane & 7) + ((lane >= 16) ? 8 : 0);
                int col = kk + ((lane & 8) ? 8 : 0);
                LDSM4(bf[q], bBase + row * 80 + col * 2);
            }
#pragma unroll
            for (int mt = 0; mt < 4; mt++)
#pragma unroll
                for (int nt = 0; nt < 8; nt++)
                    MMA16816(acc[mt][nt], af[mt],
                             bf[nt >> 1][(nt & 1) * 2], bf[nt >> 1][(nt & 1) * 2 + 1]);
        }
        __syncthreads();
    }

    // epilogue: store H + fused attention dots (one head per warp: 64 cols)
    const int head = (bn + wn) >> 6;
#pragma unroll
    for (int mt = 0; mt < 4; mt++) {
        long row0 = bm + wm + mt * 16 + (lane >> 2);
#pragma unroll
        for (int nt = 0; nt < 8; nt++) {
            int col = bn + wn + nt * 8 + (lane & 3) * 2;
            *(float2*)(Hout + row0 * 256 + col) =
                make_float2(acc[mt][nt][0], acc[mt][nt][1]);
            *(float2*)(Hout + (row0 + 8) * 256 + col) =
                make_float2(acc[mt][nt][2], acc[mt][nt][3]);
        }
#pragma unroll
        for (int r = 0; r < 2; r++) {
            float ss = 0.f, sd = 0.f;
#pragma unroll
            for (int nt = 0; nt < 8; nt++) {
                int cg = bn + wn + nt * 8 + (lane & 3) * 2;
                ss += acc[mt][nt][2 * r] * s_atts[cg] + acc[mt][nt][2 * r + 1] * s_atts[cg + 1];
                sd += acc[mt][nt][2 * r] * s_attd[cg] + acc[mt][nt][2 * r + 1] * s_attd[cg + 1];
            }
            ss += __shfl_xor_sync(0xffffffffu, ss, 1);
            ss += __shfl_xor_sync(0xffffffffu, ss, 2);
            sd += __shfl_xor_sync(0xffffffffu, sd, 1);
            sd += __shfl_xor_sync(0xffffffffu, sd, 2);
            if ((lane & 3) == 0) {
                long rg = row0 + 8 * r;
                atomicAdd(&g_asrc[rg * 4 + head], ss);
                atomicAdd(&g_adst[rg * 4 + head], sd);
            }
        }
    }
}

// ---------------- bf16 hi/lo splits ----------------
__device__ __forceinline__ void split4(float4 v, __nv_bfloat16* p) {
    __nv_bfloat16 h[4], l[4];
    float f[4] = {v.x, v.y, v.z, v.w};
#pragma unroll
    for (int i = 0; i < 4; i++) {
        h[i] = __float2bfloat16(f[i]);
        l[i] = __float2bfloat16(f[i] - __bfloat162float(h[i]));
    }
    *(uint2*)p         = *(uint2*)h;
    *(uint2*)(p + 256) = *(uint2*)l;
}

__global__ void split_a(const float4* __restrict__ X, __nv_bfloat16* __restrict__ Ae) {
    long i = (long)blockIdx.x * blockDim.x + threadIdx.x;
    if (i >= (long)TOT_NODES * 64) return;
    long m = i >> 6; int kk = (int)(i & 63) << 2;
    split4(X[i], Ae + m * KA + kk);
}

__global__ void elu_split(const float4* __restrict__ X, __nv_bfloat16* __restrict__ Ae) {
    long i = (long)blockIdx.x * blockDim.x + threadIdx.x;
    if (i >= (long)TOT_NODES * 64) return;
    float4 v = X[i];
    v.x = v.x > 0.f ? v.x : expm1f(v.x);
    v.y = v.y > 0.f ? v.y : expm1f(v.y);
    v.z = v.z > 0.f ? v.z : expm1f(v.z);
    v.w = v.w > 0.f ? v.w : expm1f(v.w);
    long m = i >> 6; int kk = (int)(i & 63) << 2;
    split4(v, Ae + m * KA + kk);
}

__global__ void split_w(const float* __restrict__ W, __nv_bfloat16* __restrict__ Be) {
    int t = blockIdx.x * blockDim.x + threadIdx.x;   // 65536
    int n = t >> 8, k = t & 255;
    float v = W[k * 256 + n];
    __nv_bfloat16 h = __float2bfloat16(v);
    __nv_bfloat16 l = __float2bfloat16(v - __bfloat162float(h));
    Be[n * KB + k]       = h;
    Be[n * KB + k + 256] = h;
    Be[n * KB + k + 512] = l;
}

// ---------------- CSR build (indices identical for both layers) ----------------
__global__ void csr_zero() {
    int i = blockIdx.x * blockDim.x + threadIdx.x;
    if (i < TOT_NODES) { g_cnt[i] = 0; g_cur[i] = 0; }
}

__global__ void csr_count(const int* __restrict__ dst) {
    int eg = blockIdx.x * blockDim.x + threadIdx.x;
    if (eg >= TOT_EDGES) return;
    int b = eg / EN, le = eg % EN;
    int d = (le < Ee) ? dst[b * Ee + le] : le - Ee;
    atomicAdd(&g_cnt[b * Nn + d], 1);
}

// one block per graph: exclusive scan of 2048 counts
__global__ __launch_bounds__(1024) void csr_scan() {
    __shared__ int ts[1024];
    int b = blockIdx.x, t = threadIdx.x;
    int base = b * Nn;
    int a0 = g_cnt[base + 2 * t], a1 = g_cnt[base + 2 * t + 1];
    ts[t] = a0 + a1;
    __syncthreads();
    for (int off = 1; off < 1024; off <<= 1) {
        int v = (t >= off) ? ts[t - off] : 0;
        __syncthreads();
        ts[t] += v;
        __syncthreads();
    }
    int ex0 = ts[t] - a0 - a1;
    g_off[base + 2 * t]     = b * EN + ex0;
    g_off[base + 2 * t + 1] = b * EN + ex0 + a0;
}

__global__ void csr_fill(const int* __restrict__ dst) {
    int eg = blockIdx.x * blockDim.x + threadIdx.x;
    if (eg >= TOT_EDGES) return;
    int b = eg / EN, le = eg % EN;
    int d = (le < Ee) ? dst[b * Ee + le] : le - Ee;
    int dn = b * Nn + d;
    int slot = g_off[dn] + atomicAdd(&g_cur[dn], 1);
    g_eid[slot] = eg;
}

// ---------------- softmax pieces ----------------
__device__ __forceinline__ unsigned f2o(float f) {
    unsigned u = __float_as_uint(f);
    return (u & 0x80000000u) ? ~u : (u | 0x80000000u);
}
__device__ __forceinline__ float o2f(unsigned u) {
    return (u & 0x80000000u) ? __uint_as_float(u & 0x7fffffffu) : __uint_as_float(~u);
}

// zero/init: m=-inf, den=0, asrc=0, adst=0 (must precede gemm: epilogue atomics)
__global__ void init_md() {
    int i = blockIdx.x * blockDim.x + threadIdx.x;
    if (i < TOT_NODES * NH) {
        g_m[i] = 0x00800000u; g_den[i] = 0.f;
        g_asrc[i] = 0.f;      g_adst[i] = 0.f;
    }
}

__global__ void edge_max(const int* __restrict__ src, const int* __restrict__ dst) {
    int idx = blockIdx.x * blockDim.x + threadIdx.x;
    if (idx >= TOT_EDGES * NH) return;
    int hd = idx & 3, eg = idx >> 2;
    int b = eg / EN, le = eg % EN;
    int s, d;
    if (le < Ee) { s = src[b * Ee + le]; d = dst[b * Ee + le]; }
    else         { s = d = le - Ee; }
    float v = g_asrc[(b * Nn + s) * 4 + hd] + g_adst[(b * Nn + d) * 4 + hd];
    v = v >= 0.f ? v : 0.2f * v;
    g_e[idx] = v;
    atomicMax(&g_m[(b * Nn + d) * 4 + hd], f2o(v));
}

__global__ void edge_exp(const int* __restrict__ dst) {
    int idx = blockIdx.x * blockDim.x + threadIdx.x;
    if (idx >= TOT_EDGES * NH) return;
    int hd = idx & 3, eg = idx >> 2;
    int b = eg / EN, le = eg % EN;
    int d = (le < Ee) ? dst[b * Ee + le] : (le - Ee);
    float mv = o2f(g_m[(b * Nn + d) * 4 + hd]);
    float x = expf(g_e[idx] - mv);
    g_e[idx] = x;
    atomicAdd(&g_den[(b * Nn + d) * 4 + hd], x);
}

// ---------------- CSR gather aggregation (warp per destination node) --------
__global__ __launch_bounds__(256) void aggr_csr(const int* __restrict__ src,
                                                const float* __restrict__ bias,
                                                float* __restrict__ out) {
    int node = (blockIdx.x * blockDim.x + threadIdx.x) >> 5;
    int lane = threadIdx.x & 31;
    if (node >= TOT_NODES) return;
    int b = node >> 11;
    int deg = g_cnt[node], off = g_off[node];
    float4 dv = *(const float4*)(g_den + (size_t)node * 4);
    float dinv[4] = {1.f / (dv.x + 1e-16f), 1.f / (dv.y + 1e-16f),
                     1.f / (dv.z + 1e-16f), 1.f / (dv.w + 1e-16f)};
    float acc[8];
#pragma unroll
    for (int jj = 0; jj < 8; jj++) acc[jj] = __ldg(bias + lane + 32 * jj);

    for (int j = 0; j < deg; j++) {
        int eg = g_eid[off + j];
        int le = eg - b * EN;
        int sn = (le < Ee) ? __ldg(src + b * Ee + le) : le - Ee;
        float4 ev = *(const float4*)(g_e + (size_t)eg * 4);
        float al[4] = {ev.x * dinv[0], ev.y * dinv[1], ev.z * dinv[2], ev.w * dinv[3]};
        const float* hrow = g_h + (size_t)(b * Nn + sn) * 256;
#pragma unroll
        for (int jj = 0; jj < 8; jj++)
            acc[jj] += al[jj >> 1] * hrow[lane + 32 * jj];
    }
    float* orow = out + (size_t)node * 256;
#pragma unroll
    for (int jj = 0; jj < 8; jj++) orow[lane + 32 * jj] = acc[jj];
}

// ---------------- launch ----------------
extern "C" void kernel_launch(void* const* d_in, const int* in_sizes, int n_in,
                              void* d_out, int out_size) {
    const float* x   = (const float*)d_in[0];
    const int*   src = (const int*)  d_in[1];
    const int*   dst = (const int*)  d_in[2];
    const float* W1  = (const float*)d_in[3];
    const float* as1 = (const float*)d_in[4];
    const float* ad1 = (const float*)d_in[5];
    const float* b1  = (const float*)d_in[6];
    const float* W2  = (const float*)d_in[7];
    const float* as2 = (const float*)d_in[8];
    const float* ad2 = (const float*)d_in[9];
    const float* b2  = (const float*)d_in[10];
    float* out = (float*)d_out;

    float *p_h, *p_x2, *p_ae_f, *p_be1_f, *p_be2_f;
    cudaGetSymbolAddress((void**)&p_h,     g_h);
    cudaGetSymbolAddress((void**)&p_x2,    g_x2);
    cudaGetSymbolAddress((void**)&p_ae_f,  g_ae);
    cudaGetSymbolAddress((void**)&p_be1_f, g_be1);
    cudaGetSymbolAddress((void**)&p_be2_f, g_be2);
    __nv_bfloat16* p_ae  = (__nv_bfloat16*)p_ae_f;
    __nv_bfloat16* p_be1 = (__nv_bfloat16*)p_be1_f;
    __nv_bfloat16* p_be2 = (__nv_bfloat16*)p_be2_f;

    const int T = 256;
    dim3 gemm_grid(TOT_NODES / 128, 2);
    int nodes_nh_blocks  = (TOT_NODES * NH + T - 1) / T;
    int edge_blocks      = (TOT_EDGES + T - 1) / T;
    int edge_h_blocks    = (TOT_EDGES * NH + T - 1) / T;
    int node_warp_blocks = TOT_NODES / (T / 32);
    int split_blocks     = (TOT_NODES * 64 + T - 1) / T;
    int nodes_blocks     = (TOT_NODES + T - 1) / T;

    // weight prep + CSR build (indices shared by both layers)
    split_w<<<256, T>>>(W1, p_be1);
    split_w<<<256, T>>>(W2, p_be2);
    csr_zero<<<nodes_blocks, T>>>();
    csr_count<<<edge_blocks, T>>>(dst);
    csr_scan<<<Bc, 1024>>>();
    csr_fill<<<edge_blocks, T>>>(dst);

    // ---------------- Layer 1 ----------------
    split_a<<<split_blocks, T>>>((const float4*)x, p_ae);
    init_md<<<nodes_nh_blocks, T>>>();
    gemm_bf16<<<gemm_grid, 128>>>(p_ae, p_be1, p_h, as1, ad1);
    edge_max<<<edge_h_blocks, T>>>(src, dst);
    edge_exp<<<edge_h_blocks, T>>>(dst);
    aggr_csr<<<node_warp_blocks, T>>>(src, b1, p_x2);

    // ---------------- Layer 2 ----------------
    elu_split<<<split_blocks, T>>>((const float4*)p_x2, p_ae);
    init_md<<<nodes_nh_blocks, T>>>();
    gemm_bf16<<<gemm_grid, 128>>>(p_ae, p_be2, p_h, as2, ad2);
    edge_max<<<edge_h_blocks, T>>>(src, dst);
    edge_exp<<<edge_h_blocks, T>>>(dst);
    aggr_csr<<<node_warp_blocks, T>>>(src, b2, out);
}

// round 15
// speedup vs baseline: 1.0028x; 1.0028x over previous
#include <cuda_runtime.h>
#include <cuda_bf16.h>
#include <math.h>
#include <cstdint>

#define Bc 32
#define Nn 2048
#define Ee 4096
#define HC 256
#define NH 4
#define EN (Ee + Nn)              // 6144
#define TOT_NODES (Bc * Nn)       // 65536
#define TOT_EDGES (Bc * EN)       // 196608
#define KA 512                    // stored A split width (hi|lo)
#define KB 768                    // B split width (hi|hi|lo) == GEMM K

// ---------------- scratch (device globals) ----------------
__device__ float         g_h  [TOT_NODES * HC];
__device__ float         g_x2 [TOT_NODES * HC];
__device__ __nv_bfloat16 g_ae [(size_t)TOT_NODES * KA];
__device__ __nv_bfloat16 g_be1[256 * KB];
__device__ __nv_bfloat16 g_be2[256 * KB];
__device__ float         g_asrc[TOT_NODES * NH];
__device__ float         g_adst[TOT_NODES * NH];
__device__ unsigned      g_m  [TOT_NODES * NH];
__device__ float         g_den[TOT_NODES * NH];
__device__ float         g_e  [TOT_EDGES * NH];
// CSR (built once per call; shared by both layers)
__device__ int           g_cnt[TOT_NODES];
__device__ int           g_cur[TOT_NODES];
__device__ int           g_off[TOT_NODES];
__device__ int           g_eid[TOT_EDGES];

__device__ __forceinline__ uint32_t smem_u32(const void* p) {
    uint32_t a;
    asm("{ .reg .u64 t; cvta.to.shared.u64 t, %1; cvt.u32.u64 %0, t; }"
        : "=r"(a) : "l"(p));
    return a;
}

#define CP_ASYNC16(dst, src) \
    asm volatile("cp.async.ca.shared.global [%0], [%1], 16;" :: "r"(dst), "l"(src))
#define CP_COMMIT() asm volatile("cp.async.commit_group;" ::: "memory")
#define CP_WAIT1()  asm volatile("cp.async.wait_group 1;" ::: "memory")
#define CP_WAIT0()  asm volatile("cp.async.wait_group 0;" ::: "memory")

#define LDSM4(R, addr) \
    asm volatile("ldmatrix.sync.aligned.m8n8.x4.shared.b16 {%0,%1,%2,%3}, [%4];" \
        : "=r"((R)[0]), "=r"((R)[1]), "=r"((R)[2]), "=r"((R)[3]) : "r"(addr))

#define MMA16816(c, a, b0r, b1r) \
    asm volatile("mma.sync.aligned.m16n8k16.row.col.f32.bf16.bf16.f32 " \
        "{%0,%1,%2,%3}, {%4,%5,%6,%7}, {%8,%9}, {%0,%1,%2,%3};" \
        : "+f"((c)[0]), "+f"((c)[1]), "+f"((c)[2]), "+f"((c)[3]) \
        : "r"((a)[0]), "r"((a)[1]), "r"((a)[2]), "r"((a)[3]), "r"(b0r), "r"(b1r))

// ---------------- bf16 HMMA GEMM, warp tile 64x64, fused attn dots ----------
// H[M,256] = Ae3[M,768] @ Be[256,768]^T (Ae3 col k -> stored col k%512).
// CTA 128x128, 128 threads (4 warps, 2x2), BK=32, cp.async double buffer.
// Epilogue: g_asrc/g_adst[row,head] += sum_col H[row,col]*att[col] (atomic).
#define ROWB 40
#define TILE_B (128 * ROWB * 2)   // bytes per buffer (A or B)

__global__ __launch_bounds__(128, 2) void gemm_bf16(
    const __nv_bfloat16* __restrict__ Ae, const __nv_bfloat16* __restrict__ Be,
    float* __restrict__ Hout,
    const float* __restrict__ att_s, const float* __restrict__ att_d) {

    __shared__ __align__(16) __nv_bfloat16 sA[2][128][ROWB];
    __shared__ __align__(16) __nv_bfloat16 sB[2][128][ROWB];
    __shared__ float s_atts[256], s_attd[256];

    const int tid = threadIdx.x;
    const int wid = tid >> 5, lane = tid & 31;
    const int wm = (wid & 1) * 64;
    const int wn = (wid >> 1) * 64;
    const long bm = (long)blockIdx.x * 128;
    const int  bn = blockIdx.y * 128;

    s_atts[tid] = att_s[tid];       s_attd[tid] = att_d[tid];
    s_atts[tid + 128] = att_s[tid + 128]; s_attd[tid + 128] = att_d[tid + 128];

    const uint32_t sA_u = smem_u32(&sA[0][0][0]);
    const uint32_t sB_u = smem_u32(&sB[0][0][0]);

    float acc[4][8][4];
#pragma unroll
    for (int i = 0; i < 4; i++)
#pragma unroll
        for (int j = 0; j < 8; j++)
#pragma unroll
            for (int r = 0; r < 4; r++) acc[i][j][r] = 0.f;

    const int lr = tid >> 2;        // 0..31
    const int lc = tid & 3;         // 16B chunk

    auto loadAB = [&](int chunk, int buf) {
        int k = chunk * 32 + lc * 8;
        int sk = (k < KA) ? k : k - KA;
#pragma unroll
        for (int i = 0; i < 4; i++) {
            int r = lr + i * 32;
            CP_ASYNC16(sA_u + buf * TILE_B + r * 80 + lc * 16,
                       Ae + (size_t)(bm + r) * KA + sk);
            CP_ASYNC16(sB_u + buf * TILE_B + r * 80 + lc * 16,
                       Be + (size_t)(bn + r) * KB + k);
        }
    };

    loadAB(0, 0);
    CP_COMMIT();

    const int NCH = KB / 32;   // 24
#pragma unroll 1
    for (int c = 0; c < NCH; c++) {
        int buf = c & 1;
        if (c + 1 < NCH) { loadAB(c + 1, buf ^ 1); CP_COMMIT(); CP_WAIT1(); }
        else            { CP_WAIT0(); }
        __syncthreads();

        const uint32_t aBase = sA_u + buf * TILE_B;
        const uint32_t bBase = sB_u + buf * TILE_B;
#pragma unroll
        for (int kk = 0; kk < 32; kk += 16) {
            uint32_t af[4][4];
#pragma unroll
            for (int mt = 0; mt < 4; mt++) {
                int row = wm + mt * 16 + (lane & 15);
                int col = kk + ((lane >= 16) ? 8 : 0);
                LDSM4(af[mt], aBase + row * 80 + col * 2);
            }
            uint32_t bf[4][4];
#pragma unroll
            for (int q = 0; q < 4; q++) {
                int row = wn + q * 16 + (lane & 7) + ((lane >= 16) ? 8 : 0);
                int col = kk + ((lane & 8) ? 8 : 0);
                LDSM4(bf[q], bBase + row * 80 + col * 2);
            }
#pragma unroll
            for (int mt = 0; mt < 4; mt++)
#pragma unroll
                for (int nt = 0; nt < 8; nt++)
                    MMA16816(acc[mt][nt], af[mt],
                             bf[nt >> 1][(nt & 1) * 2], bf[nt >> 1][(nt & 1) * 2 + 1]);
        }
        __syncthreads();
    }

    // epilogue: store H + fused attention dots (one head per warp: 64 cols)
    const int head = (bn + wn) >> 6;
#pragma unroll
    for (int mt = 0; mt < 4; mt++) {
        long row0 = bm + wm + mt * 16 + (lane >> 2);
#pragma unroll
        for (int nt = 0; nt < 8; nt++) {
            int col = bn + wn + nt * 8 + (lane & 3) * 2;
            *(float2*)(Hout + row0 * 256 + col) =
                make_float2(acc[mt][nt][0], acc[mt][nt][1]);
            *(float2*)(Hout + (row0 + 8) * 256 + col) =
                make_float2(acc[mt][nt][2], acc[mt][nt][3]);
        }
#pragma unroll
        for (int r = 0; r < 2; r++) {
            float ss = 0.f, sd = 0.f;
#pragma unroll
            for (int nt = 0; nt < 8; nt++) {
                int cg = bn + wn + nt * 8 + (lane & 3) * 2;
                ss += acc[mt][nt][2 * r] * s_atts[cg] + acc[mt][nt][2 * r + 1] * s_atts[cg + 1];
                sd += acc[mt][nt][2 * r] * s_attd[cg] + acc[mt][nt][2 * r + 1] * s_attd[cg + 1];
            }
            ss += __shfl_xor_sync(0xffffffffu, ss, 1);
            ss += __shfl_xor_sync(0xffffffffu, ss, 2);
            sd += __shfl_xor_sync(0xffffffffu, sd, 1);
            sd += __shfl_xor_sync(0xffffffffu, sd, 2);
            if ((lane & 3) == 0) {
                long rg = row0 + 8 * r;
                atomicAdd(&g_asrc[rg * 4 + head], ss);
                atomicAdd(&g_adst[rg * 4 + head], sd);
            }
        }
    }
}

// ---------------- bf16 hi/lo splits ----------------
__device__ __forceinline__ void split4(float4 v, __nv_bfloat16* p) {
    __nv_bfloat16 h[4], l[4];
    float f[4] = {v.x, v.y, v.z, v.w};
#pragma unroll
    for (int i = 0; i < 4; i++) {
        h[i] = __float2bfloat16(f[i]);
        l[i] = __float2bfloat16(f[i] - __bfloat162float(h[i]));
    }
    *(uint2*)p         = *(uint2*)h;
    *(uint2*)(p + 256) = *(uint2*)l;
}

__global__ void split_a(const float4* __restrict__ X, __nv_bfloat16* __restrict__ Ae) {
    long i = (long)blockIdx.x * blockDim.x + threadIdx.x;
    if (i >= (long)TOT_NODES * 64) return;
    long m = i >> 6; int kk = (int)(i & 63) << 2;
    split4(X[i], Ae + m * KA + kk);
}

__global__ void elu_split(const float4* __restrict__ X, __nv_bfloat16* __restrict__ Ae) {
    long i = (long)blockIdx.x * blockDim.x + threadIdx.x;
    if (i >= (long)TOT_NODES * 64) return;
    float4 v = X[i];
    v.x = v.x > 0.f ? v.x : expm1f(v.x);
    v.y = v.y > 0.f ? v.y : expm1f(v.y);
    v.z = v.z > 0.f ? v.z : expm1f(v.z);
    v.w = v.w > 0.f ? v.w : expm1f(v.w);
    long m = i >> 6; int kk = (int)(i & 63) << 2;
    split4(v, Ae + m * KA + kk);
}

__global__ void split_w(const float* __restrict__ W, __nv_bfloat16* __restrict__ Be) {
    int t = blockIdx.x * blockDim.x + threadIdx.x;   // 65536
    int n = t >> 8, k = t & 255;
    float v = W[k * 256 + n];
    __nv_bfloat16 h = __float2bfloat16(v);
    __nv_bfloat16 l = __float2bfloat16(v - __bfloat162float(h));
    Be[n * KB + k]       = h;
    Be[n * KB + k + 256] = h;
    Be[n * KB + k + 512] = l;
}

// ---------------- CSR build (indices identical for both layers) ----------------
__global__ void csr_zero() {
    int i = blockIdx.x * blockDim.x + threadIdx.x;
    if (i < TOT_NODES) { g_cnt[i] = 0; g_cur[i] = 0; }
}

__global__ void csr_count(const int* __restrict__ dst) {
    int eg = blockIdx.x * blockDim.x + threadIdx.x;
    if (eg >= TOT_EDGES) return;
    int b = eg / EN, le = eg % EN;
    int d = (le < Ee) ? dst[b * Ee + le] : le - Ee;
    atomicAdd(&g_cnt[b * Nn + d], 1);
}

// one block per graph: exclusive scan of 2048 counts
__global__ __launch_bounds__(1024) void csr_scan() {
    __shared__ int ts[1024];
    int b = blockIdx.x, t = threadIdx.x;
    int base = b * Nn;
    int a0 = g_cnt[base + 2 * t], a1 = g_cnt[base + 2 * t + 1];
    ts[t] = a0 + a1;
    __syncthreads();
    for (int off = 1; off < 1024; off <<= 1) {
        int v = (t >= off) ? ts[t - off] : 0;
        __syncthreads();
        ts[t] += v;
        __syncthreads();
    }
    int ex0 = ts[t] - a0 - a1;
    g_off[base + 2 * t]     = b * EN + ex0;
    g_off[base + 2 * t + 1] = b * EN + ex0 + a0;
}

__global__ void csr_fill(const int* __restrict__ dst) {
    int eg = blockIdx.x * blockDim.x + threadIdx.x;
    if (eg >= TOT_EDGES) return;
    int b = eg / EN, le = eg % EN;
    int d = (le < Ee) ? dst[b * Ee + le] : le - Ee;
    int dn = b * Nn + d;
    int slot = g_off[dn] + atomicAdd(&g_cur[dn], 1);
    g_eid[slot] = eg;
}

// ---------------- softmax pieces ----------------
__device__ __forceinline__ unsigned f2o(float f) {
    unsigned u = __float_as_uint(f);
    return (u & 0x80000000u) ? ~u : (u | 0x80000000u);
}
__device__ __forceinline__ float o2f(unsigned u) {
    return (u & 0x80000000u) ? __uint_as_float(u & 0x7fffffffu) : __uint_as_float(~u);
}

// zero/init: m=-inf, den=0, asrc=0, adst=0 (must precede gemm: epilogue atomics)
__global__ void init_md() {
    int i = blockIdx.x * blockDim.x + threadIdx.x;
    if (i < TOT_NODES * NH) {
        g_m[i] = 0x00800000u; g_den[i] = 0.f;
        g_asrc[i] = 0.f;      g_adst[i] = 0.f;
    }
}

__global__ void edge_max(const int* __restrict__ src, const int* __restrict__ dst) {
    int idx = blockIdx.x * blockDim.x + threadIdx.x;
    if (idx >= TOT_EDGES * NH) return;
    int hd = idx & 3, eg = idx >> 2;
    int b = eg / EN, le = eg % EN;
    int s, d;
    if (le < Ee) { s = src[b * Ee + le]; d = dst[b * Ee + le]; }
    else         { s = d = le - Ee; }
    float v = g_asrc[(b * Nn + s) * 4 + hd] + g_adst[(b * Nn + d) * 4 + hd];
    v = v >= 0.f ? v : 0.2f * v;
    g_e[idx] = v;
    atomicMax(&g_m[(b * Nn + d) * 4 + hd], f2o(v));
}

__global__ void edge_exp(const int* __restrict__ dst) {
    int idx = blockIdx.x * blockDim.x + threadIdx.x;
    if (idx >= TOT_EDGES * NH) return;
    int hd = idx & 3, eg = idx >> 2;
    int b = eg / EN, le = eg % EN;
    int d = (le < Ee) ? dst[b * Ee + le] : (le - Ee);
    float mv = o2f(g_m[(b * Nn + d) * 4 + hd]);
    float x = expf(g_e[idx] - mv);
    g_e[idx] = x;
    atomicAdd(&g_den[(b * Nn + d) * 4 + hd], x);
}

// ---------------- CSR gather aggregation (warp per destination node) --------
__global__ __launch_bounds__(256) void aggr_csr(const int* __restrict__ src,
                                                const float* __restrict__ bias,
                                                float* __restrict__ out) {
    int node = (blockIdx.x * blockDim.x + threadIdx.x) >> 5;
    int lane = threadIdx.x & 31;
    if (node >= TOT_NODES) return;
    int b = node >> 11;
    int deg = g_cnt[node], off = g_off[node];
    float4 dv = *(const float4*)(g_den + (size_t)node * 4);
    float dinv[4] = {1.f / (dv.x + 1e-16f), 1.f / (dv.y + 1e-16f),
                     1.f / (dv.z + 1e-16f), 1.f / (dv.w + 1e-16f)};
    float acc[8];
#pragma unroll
    for (int jj = 0; jj < 8; jj++) acc[jj] = __ldg(bias + lane + 32 * jj);

    for (int j = 0; j < deg; j++) {
        int eg = g_eid[off + j];
        int le = eg - b * EN;
        int sn = (le < Ee) ? __ldg(src + b * Ee + le) : le - Ee;
        float4 ev = *(const float4*)(g_e + (size_t)eg * 4);
        float al[4] = {ev.x * dinv[0], ev.y * dinv[1], ev.z * dinv[2], ev.w * dinv[3]};
        const float* hrow = g_h + (size_t)(b * Nn + sn) * 256;
#pragma unroll
        for (int jj = 0; jj < 8; jj++)
            acc[jj] += al[jj >> 1] * hrow[lane + 32 * jj];
    }
    float* orow = out + (size_t)node * 256;
#pragma unroll
    for (int jj = 0; jj < 8; jj++) orow[lane + 32 * jj] = acc[jj];
}

// ---------------- launch ----------------
extern "C" void kernel_launch(void* const* d_in, const int* in_sizes, int n_in,
                              void* d_out, int out_size) {
    const float* x   = (const float*)d_in[0];
    const int*   src = (const int*)  d_in[1];
    const int*   dst = (const int*)  d_in[2];
    const float* W1  = (const float*)d_in[3];
    const float* as1 = (const float*)d_in[4];
    const float* ad1 = (const float*)d_in[5];
    const float* b1  = (const float*)d_in[6];
    const float* W2  = (const float*)d_in[7];
    const float* as2 = (const float*)d_in[8];
    const float* ad2 = (const float*)d_in[9];
    const float* b2  = (const float*)d_in[10];
    float* out = (float*)d_out;

    float *p_h, *p_x2, *p_ae_f, *p_be1_f, *p_be2_f;
    cudaGetSymbolAddress((void**)&p_h,     g_h);
    cudaGetSymbolAddress((void**)&p_x2,    g_x2);
    cudaGetSymbolAddress((void**)&p_ae_f,  g_ae);
    cudaGetSymbolAddress((void**)&p_be1_f, g_be1);
    cudaGetSymbolAddress((void**)&p_be2_f, g_be2);
    __nv_bfloat16* p_ae  = (__nv_bfloat16*)p_ae_f;
    __nv_bfloat16* p_be1 = (__nv_bfloat16*)p_be1_f;
    __nv_bfloat16* p_be2 = (__nv_bfloat16*)p_be2_f;

    const int T = 256;
    dim3 gemm_grid(TOT_NODES / 128, 2);
    int nodes_nh_blocks  = (TOT_NODES * NH + T - 1) / T;
    int edge_blocks      = (TOT_EDGES + T - 1) / T;
    int edge_h_blocks    = (TOT_EDGES * NH + T - 1) / T;
    int node_warp_blocks = TOT_NODES / (T / 32);
    int split_blocks     = (TOT_NODES * 64 + T - 1) / T;
    int nodes_blocks     = (TOT_NODES + T - 1) / T;

    // weight prep + CSR build (indices shared by both layers)
    split_w<<<256, T>>>(W1, p_be1);
    split_w<<<256, T>>>(W2, p_be2);
    csr_zero<<<nodes_blocks, T>>>();
    csr_count<<<edge_blocks, T>>>(dst);
    csr_scan<<<Bc, 1024>>>();
    csr_fill<<<edge_blocks, T>>>(dst);

    // ---------------- Layer 1 ----------------
    split_a<<<split_blocks, T>>>((const float4*)x, p_ae);
    init_md<<<nodes_nh_blocks, T>>>();
    gemm_bf16<<<gemm_grid, 128>>>(p_ae, p_be1, p_h, as1, ad1);
    edge_max<<<edge_h_blocks, T>>>(src, dst);
    edge_exp<<<edge_h_blocks, T>>>(dst);
    aggr_csr<<<node_warp_blocks, T>>>(src, b1, p_x2);

    // ---------------- Layer 2 ----------------
    elu_split<<<split_blocks, T>>>((const float4*)p_x2, p_ae);
    init_md<<<nodes_nh_blocks, T>>>();
    gemm_bf16<<<gemm_grid, 128>>>(p_ae, p_be2, p_h, as2, ad2);
    edge_max<<<edge_h_blocks, T>>>(src, dst);
    edge_exp<<<edge_h_blocks, T>>>(dst);
    aggr_csr<<<node_warp_blocks, T>>>(src, b2, out);
}

// round 16
// speedup vs baseline: 1.0033x; 1.0005x over previous
#include <cuda_runtime.h>
#include <cuda_bf16.h>
#include <math.h>
#include <cstdint>

#define Bc 32
#define Nn 2048
#define Ee 4096
#define HC 256
#define NH 4
#define EN (Ee + Nn)              // 6144
#define TOT_NODES (Bc * Nn)       // 65536
#define TOT_EDGES (Bc * EN)       // 196608
#define KA 512                    // stored A split width (hi|lo)
#define KB 768                    // B split width (hi|hi|lo) == GEMM K

// ---------------- scratch (device globals) ----------------
__device__ float         g_h  [TOT_NODES * HC];
__device__ float         g_x2 [TOT_NODES * HC];
__device__ __nv_bfloat16 g_ae [(size_t)TOT_NODES * KA];
__device__ __nv_bfloat16 g_be1[256 * KB];
__device__ __nv_bfloat16 g_be2[256 * KB];
__device__ float         g_asrc[TOT_NODES * NH];
__device__ float         g_adst[TOT_NODES * NH];
__device__ unsigned      g_m  [TOT_NODES * NH];
__device__ float         g_den[TOT_NODES * NH];
__device__ float         g_e  [TOT_EDGES * NH];
// CSR (built once per call; shared by both layers)
__device__ int           g_cnt[TOT_NODES];
__device__ int           g_cur[TOT_NODES];
__device__ int           g_off[TOT_NODES];
__device__ int           g_eid[TOT_EDGES];

__device__ __forceinline__ uint32_t smem_u32(const void* p) {
    uint32_t a;
    asm("{ .reg .u64 t; cvta.to.shared.u64 t, %1; cvt.u32.u64 %0, t; }"
        : "=r"(a) : "l"(p));
    return a;
}

#define CP_ASYNC16(dst, src) \
    asm volatile("cp.async.ca.shared.global [%0], [%1], 16;" :: "r"(dst), "l"(src))
#define CP_COMMIT() asm volatile("cp.async.commit_group;" ::: "memory")
#define CP_WAIT1()  asm volatile("cp.async.wait_group 1;" ::: "memory")
#define CP_WAIT0()  asm volatile("cp.async.wait_group 0;" ::: "memory")

#define LDSM4(R, addr) \
    asm volatile("ldmatrix.sync.aligned.m8n8.x4.shared.b16 {%0,%1,%2,%3}, [%4];" \
        : "=r"((R)[0]), "=r"((R)[1]), "=r"((R)[2]), "=r"((R)[3]) : "r"(addr))

#define MMA16816(c, a, b0r, b1r) \
    asm volatile("mma.sync.aligned.m16n8k16.row.col.f32.bf16.bf16.f32 " \
        "{%0,%1,%2,%3}, {%4,%5,%6,%7}, {%8,%9}, {%0,%1,%2,%3};" \
        : "+f"((c)[0]), "+f"((c)[1]), "+f"((c)[2]), "+f"((c)[3]) \
        : "r"((a)[0]), "r"((a)[1]), "r"((a)[2]), "r"((a)[3]), "r"(b0r), "r"(b1r))

// ---------------- bf16 HMMA GEMM, warp tile 64x64, fused attn dots ----------
// H[M,256] = Ae3[M,768] @ Be[256,768]^T (Ae3 col k -> stored col k%512).
// CTA 128x128, 128 threads (4 warps, 2x2), BK=32, cp.async double buffer.
// Epilogue: g_asrc/g_adst[row,head] += sum_col H[row,col]*att[col] (atomic).
#define ROWB 40
#define TILE_B (128 * ROWB * 2)   // bytes per buffer (A or B)

__global__ __launch_bounds__(128, 2) void gemm_bf16(
    const __nv_bfloat16* __restrict__ Ae, const __nv_bfloat16* __restrict__ Be,
    float* __restrict__ Hout,
    const float* __restrict__ att_s, const float* __restrict__ att_d) {

    __shared__ __align__(16) __nv_bfloat16 sA[2][128][ROWB];
    __shared__ __align__(16) __nv_bfloat16 sB[2][128][ROWB];
    __shared__ float s_atts[256], s_attd[256];

    const int tid = threadIdx.x;
    const int wid = tid >> 5, lane = tid & 31;
    const int wm = (wid & 1) * 64;
    const int wn = (wid >> 1) * 64;
    const long bm = (long)blockIdx.x * 128;
    const int  bn = blockIdx.y * 128;

    s_atts[tid] = att_s[tid];       s_attd[tid] = att_d[tid];
    s_atts[tid + 128] = att_s[tid + 128]; s_attd[tid + 128] = att_d[tid + 128];

    const uint32_t sA_u = smem_u32(&sA[0][0][0]);
    const uint32_t sB_u = smem_u32(&sB[0][0][0]);

    float acc[4][8][4];
#pragma unroll
    for (int i = 0; i < 4; i++)
#pragma unroll
        for (int j = 0; j < 8; j++)
#pragma unroll
            for (int r = 0; r < 4; r++) acc[i][j][r] = 0.f;

    const int lr = tid >> 2;        // 0..31
    const int lc = tid & 3;         // 16B chunk

    auto loadAB = [&](int chunk, int buf) {
        int k = chunk * 32 + lc * 8;
        int sk = (k < KA) ? k : k - KA;
#pragma unroll
        for (int i = 0; i < 4; i++) {
            int r = lr + i * 32;
            CP_ASYNC16(sA_u + buf * TILE_B + r * 80 + lc * 16,
                       Ae + (size_t)(bm + r) * KA + sk);
            CP_ASYNC16(sB_u + buf * TILE_B + r * 80 + lc * 16,
                       Be + (size_t)(bn + r) * KB + k);
        }
    };

    loadAB(0, 0);
    CP_COMMIT();

    const int NCH = KB / 32;   // 24
#pragma unroll 1
    for (int c = 0; c < NCH; c++) {
        int buf = c & 1;
        if (c + 1 < NCH) { loadAB(c + 1, buf ^ 1); CP_COMMIT(); CP_WAIT1(); }
        else            { CP_WAIT0(); }
        __syncthreads();

        const uint32_t aBase = sA_u + buf * TILE_B;
        const uint32_t bBase = sB_u + buf * TILE_B;
#pragma unroll
        for (int kk = 0; kk < 32; kk += 16) {
            uint32_t af[4][4];
#pragma unroll
            for (int mt = 0; mt < 4; mt++) {
                int row = wm + mt * 16 + (lane & 15);
                int col = kk + ((lane >= 16) ? 8 : 0);
                LDSM4(af[mt], aBase + row * 80 + col * 2);
            }
            uint32_t bf[4][4];
#pragma unroll
            for (int q = 0; q < 4; q++) {
                int row = wn + q * 16 + (lane & 7) + ((lane >= 16) ? 8 : 0);
                int col = kk + ((lane & 8) ? 8 : 0);
                LDSM4(bf[q], bBase + row * 80 + col * 2);
            }
#pragma unroll
            for (int mt = 0; mt < 4; mt++)
#pragma unroll
                for (int nt = 0; nt < 8; nt++)
                    MMA16816(acc[mt][nt], af[mt],
                             bf[nt >> 1][(nt & 1) * 2], bf[nt >> 1][(nt & 1) * 2 + 1]);
        }
        __syncthreads();
    }

    // epilogue: store H + fused attention dots (one head per warp: 64 cols)
    const int head = (bn + wn) >> 6;
#pragma unroll
    for (int mt = 0; mt < 4; mt++) {
        long row0 = bm + wm + mt * 16 + (lane >> 2);
#pragma unroll
        for (int nt = 0; nt < 8; nt++) {
            int col = bn + wn + nt * 8 + (lane & 3) * 2;
            *(float2*)(Hout + row0 * 256 + col) =
                make_float2(acc[mt][nt][0], acc[mt][nt][1]);
            *(float2*)(Hout + (row0 + 8) * 256 + col) =
                make_float2(acc[mt][nt][2], acc[mt][nt][3]);
        }
#pragma unroll
        for (int r = 0; r < 2; r++) {
            float ss = 0.f, sd = 0.f;
#pragma unroll
            for (int nt = 0; nt < 8; nt++) {
                int cg = bn + wn + nt * 8 + (lane & 3) * 2;
                ss += acc[mt][nt][2 * r] * s_atts[cg] + acc[mt][nt][2 * r + 1] * s_atts[cg + 1];
                sd += acc[mt][nt][2 * r] * s_attd[cg] + acc[mt][nt][2 * r + 1] * s_attd[cg + 1];
            }
            ss += __shfl_xor_sync(0xffffffffu, ss, 1);
            ss += __shfl_xor_sync(0xffffffffu, ss, 2);
            sd += __shfl_xor_sync(0xffffffffu, sd, 1);
            sd += __shfl_xor_sync(0xffffffffu, sd, 2);
            if ((lane & 3) == 0) {
                long rg = row0 + 8 * r;
                atomicAdd(&g_asrc[rg * 4 + head], ss);
                atomicAdd(&g_adst[rg * 4 + head], sd);
            }
        }
    }
}

// ---------------- bf16 hi/lo splits ----------------
__device__ __forceinline__ void split4(float4 v, __nv_bfloat16* p) {
    __nv_bfloat16 h[4], l[4];
    float f[4] = {v.x, v.y, v.z, v.w};
#pragma unroll
    for (int i = 0; i < 4; i++) {
        h[i] = __float2bfloat16(f[i]);
        l[i] = __float2bfloat16(f[i] - __bfloat162float(h[i]));
    }
    *(uint2*)p         = *(uint2*)h;
    *(uint2*)(p + 256) = *(uint2*)l;
}

__global__ void split_a(const float4* __restrict__ X, __nv_bfloat16* __restrict__ Ae) {
    long i = (long)blockIdx.x * blockDim.x + threadIdx.x;
    if (i >= (long)TOT_NODES * 64) return;
    long m = i >> 6; int kk = (int)(i & 63) << 2;
    split4(X[i], Ae + m * KA + kk);
}

__global__ void elu_split(const float4* __restrict__ X, __nv_bfloat16* __restrict__ Ae) {
    long i = (long)blockIdx.x * blockDim.x + threadIdx.x;
    if (i >= (long)TOT_NODES * 64) return;
    float4 v = X[i];
    v.x = v.x > 0.f ? v.x : expm1f(v.x);
    v.y = v.y > 0.f ? v.y : expm1f(v.y);
    v.z = v.z > 0.f ? v.z : expm1f(v.z);
    v.w = v.w > 0.f ? v.w : expm1f(v.w);
    long m = i >> 6; int kk = (int)(i & 63) << 2;
    split4(v, Ae + m * KA + kk);
}

__global__ void split_w(const float* __restrict__ W, __nv_bfloat16* __restrict__ Be) {
    int t = blockIdx.x * blockDim.x + threadIdx.x;   // 65536
    int n = t >> 8, k = t & 255;
    float v = W[k * 256 + n];
    __nv_bfloat16 h = __float2bfloat16(v);
    __nv_bfloat16 l = __float2bfloat16(v - __bfloat162float(h));
    Be[n * KB + k]       = h;
    Be[n * KB + k + 256] = h;
    Be[n * KB + k + 512] = l;
}

// ---------------- CSR build (indices identical for both layers) ----------------
__global__ void csr_zero() {
    int i = blockIdx.x * blockDim.x + threadIdx.x;
    if (i < TOT_NODES) { g_cnt[i] = 0; g_cur[i] = 0; }
}

__global__ void csr_count(const int* __restrict__ dst) {
    int eg = blockIdx.x * blockDim.x + threadIdx.x;
    if (eg >= TOT_EDGES) return;
    int b = eg / EN, le = eg % EN;
    int d = (le < Ee) ? dst[b * Ee + le] : le - Ee;
    atomicAdd(&g_cnt[b * Nn + d], 1);
}

// one block per graph: exclusive scan of 2048 counts
__global__ __launch_bounds__(1024) void csr_scan() {
    __shared__ int ts[1024];
    int b = blockIdx.x, t = threadIdx.x;
    int base = b * Nn;
    int a0 = g_cnt[base + 2 * t], a1 = g_cnt[base + 2 * t + 1];
    ts[t] = a0 + a1;
    __syncthreads();
    for (int off = 1; off < 1024; off <<= 1) {
        int v = (t >= off) ? ts[t - off] : 0;
        __syncthreads();
        ts[t] += v;
        __syncthreads();
    }
    int ex0 = ts[t] - a0 - a1;
    g_off[base + 2 * t]     = b * EN + ex0;
    g_off[base + 2 * t + 1] = b * EN + ex0 + a0;
}

__global__ void csr_fill(const int* __restrict__ dst) {
    int eg = blockIdx.x * blockDim.x + threadIdx.x;
    if (eg >= TOT_EDGES) return;
    int b = eg / EN, le = eg % EN;
    int d = (le < Ee) ? dst[b * Ee + le] : le - Ee;
    int dn = b * Nn + d;
    int slot = g_off[dn] + atomicAdd(&g_cur[dn], 1);
    g_eid[slot] = eg;
}

// ---------------- softmax pieces ----------------
__device__ __forceinline__ unsigned f2o(float f) {
    unsigned u = __float_as_uint(f);
    return (u & 0x80000000u) ? ~u : (u | 0x80000000u);
}
__device__ __forceinline__ float o2f(unsigned u) {
    return (u & 0x80000000u) ? __uint_as_float(u & 0x7fffffffu) : __uint_as_float(~u);
}

// zero/init: m=-inf, den=0, asrc=0, adst=0 (must precede gemm: epilogue atomics)
__global__ void init_md() {
    int i = blockIdx.x * blockDim.x + threadIdx.x;
    if (i < TOT_NODES * NH) {
        g_m[i] = 0x00800000u; g_den[i] = 0.f;
        g_asrc[i] = 0.f;      g_adst[i] = 0.f;
    }
}

__global__ void edge_max(const int* __restrict__ src, const int* __restrict__ dst) {
    int idx = blockIdx.x * blockDim.x + threadIdx.x;
    if (idx >= TOT_EDGES * NH) return;
    int hd = idx & 3, eg = idx >> 2;
    int b = eg / EN, le = eg % EN;
    int s, d;
    if (le < Ee) { s = src[b * Ee + le]; d = dst[b * Ee + le]; }
    else         { s = d = le - Ee; }
    float v = g_asrc[(b * Nn + s) * 4 + hd] + g_adst[(b * Nn + d) * 4 + hd];
    v = v >= 0.f ? v : 0.2f * v;
    g_e[idx] = v;
    atomicMax(&g_m[(b * Nn + d) * 4 + hd], f2o(v));
}

__global__ void edge_exp(const int* __restrict__ dst) {
    int idx = blockIdx.x * blockDim.x + threadIdx.x;
    if (idx >= TOT_EDGES * NH) return;
    int hd = idx & 3, eg = idx >> 2;
    int b = eg / EN, le = eg % EN;
    int d = (le < Ee) ? dst[b * Ee + le] : (le - Ee);
    float mv = o2f(g_m[(b * Nn + d) * 4 + hd]);
    float x = expf(g_e[idx] - mv);
    g_e[idx] = x;
    atomicAdd(&g_den[(b * Nn + d) * 4 + hd], x);
}

// ---------------- CSR gather aggregation (warp per destination node) --------
__global__ __launch_bounds__(256) void aggr_csr(const int* __restrict__ src,
                                                const float* __restrict__ bias,
                                                float* __restrict__ out) {
    int node = (blockIdx.x * blockDim.x + threadIdx.x) >> 5;
    int lane = threadIdx.x & 31;
    if (node >= TOT_NODES) return;
    int b = node >> 11;
    int deg = g_cnt[node], off = g_off[node];
    float4 dv = *(const float4*)(g_den + (size_t)node * 4);
    float dinv[4] = {1.f / (dv.x + 1e-16f), 1.f / (dv.y + 1e-16f),
                     1.f / (dv.z + 1e-16f), 1.f / (dv.w + 1e-16f)};
    float acc[8];
#pragma unroll
    for (int jj = 0; jj < 8; jj++) acc[jj] = __ldg(bias + lane + 32 * jj);

    for (int j = 0; j < deg; j++) {
        int eg = g_eid[off + j];
        int le = eg - b * EN;
        int sn = (le < Ee) ? __ldg(src + b * Ee + le) : le - Ee;
        float4 ev = *(const float4*)(g_e + (size_t)eg * 4);
        float al[4] = {ev.x * dinv[0], ev.y * dinv[1], ev.z * dinv[2], ev.w * dinv[3]};
        const float* hrow = g_h + (size_t)(b * Nn + sn) * 256;
#pragma unroll
        for (int jj = 0; jj < 8; jj++)
            acc[jj] += al[jj >> 1] * hrow[lane + 32 * jj];
    }
    float* orow = out + (size_t)node * 256;
#pragma unroll
    for (int jj = 0; jj < 8; jj++) orow[lane + 32 * jj] = acc[jj];
}

// ---------------- launch ----------------
extern "C" void kernel_launch(void* const* d_in, const int* in_sizes, int n_in,
                              void* d_out, int out_size) {
    const float* x   = (const float*)d_in[0];
    const int*   src = (const int*)  d_in[1];
    const int*   dst = (const int*)  d_in[2];
    const float* W1  = (const float*)d_in[3];
    const float* as1 = (const float*)d_in[4];
    const float* ad1 = (const float*)d_in[5];
    const float* b1  = (const float*)d_in[6];
    const float* W2  = (const float*)d_in[7];
    const float* as2 = (const float*)d_in[8];
    const float* ad2 = (const float*)d_in[9];
    const float* b2  = (const float*)d_in[10];
    float* out = (float*)d_out;

    float *p_h, *p_x2, *p_ae_f, *p_be1_f, *p_be2_f;
    cudaGetSymbolAddress((void**)&p_h,     g_h);
    cudaGetSymbolAddress((void**)&p_x2,    g_x2);
    cudaGetSymbolAddress((void**)&p_ae_f,  g_ae);
    cudaGetSymbolAddress((void**)&p_be1_f, g_be1);
    cudaGetSymbolAddress((void**)&p_be2_f, g_be2);
    __nv_bfloat16* p_ae  = (__nv_bfloat16*)p_ae_f;
    __nv_bfloat16* p_be1 = (__nv_bfloat16*)p_be1_f;
    __nv_bfloat16* p_be2 = (__nv_bfloat16*)p_be2_f;

    const int T = 256;
    dim3 gemm_grid(TOT_NODES / 128, 2);
    int nodes_nh_blocks  = (TOT_NODES * NH + T - 1) / T;
    int edge_blocks      = (TOT_EDGES + T - 1) / T;
    int edge_h_blocks    = (TOT_EDGES * NH + T - 1) / T;
    int node_warp_blocks = TOT_NODES / (T / 32);
    int split_blocks     = (TOT_NODES * 64 + T - 1) / T;
    int nodes_blocks     = (TOT_NODES + T - 1) / T;

    // weight prep + CSR build (indices shared by both layers)
    split_w<<<256, T>>>(W1, p_be1);
    split_w<<<256, T>>>(W2, p_be2);
    csr_zero<<<nodes_blocks, T>>>();
    csr_count<<<edge_blocks, T>>>(dst);
    csr_scan<<<Bc, 1024>>>();
    csr_fill<<<edge_blocks, T>>>(dst);

    // ---------------- Layer 1 ----------------
    split_a<<<split_blocks, T>>>((const float4*)x, p_ae);
    init_md<<<nodes_nh_blocks, T>>>();
    gemm_bf16<<<gemm_grid, 128>>>(p_ae, p_be1, p_h, as1, ad1);
    edge_max<<<edge_h_blocks, T>>>(src, dst);
    edge_exp<<<edge_h_blocks, T>>>(dst);
    aggr_csr<<<node_warp_blocks, T>>>(src, b1, p_x2);

    // ---------------- Layer 2 ----------------
    elu_split<<<split_blocks, T>>>((const float4*)p_x2, p_ae);
    init_md<<<nodes_nh_blocks, T>>>();
    gemm_bf16<<<gemm_grid, 128>>>(p_ae, p_be2, p_h, as2, ad2);
    edge_max<<<edge_h_blocks, T>>>(src, dst);
    edge_exp<<<edge_h_blocks, T>>>(dst);
    aggr_csr<<<node_warp_blocks, T>>>(src, b2, out);
}